// round 13
// baseline (speedup 1.0000x reference)
#include <cuda_runtime.h>
#include <cuda_fp16.h>

#define IN_F 256
#define NHEAD 8
#define OUT_F 64
#define TMAX 8
#define MAXN 100000
#define MAXE 3200000

typedef unsigned long long ull;

// Scratch (static __device__ — no allocations allowed)
__device__ float g_A[IN_F * 16];        // [i][0..7]=A_l, [i][8..15]=A_r
__device__ float g_ee[TMAX * NHEAD];    // per-etype logit table
// el/er as fp16: one 16B record per node (8 halfs), single LDG.128 gather
__device__ uint4 g_elh[MAXN];
__device__ uint4 g_erh[MAXN];
// softmax denominator, fp32 (atomic target), 32B per node record
__device__ float4 g_s4[MAXN * 2];
// 1/s packed fp16x8: one 16B record per node -> finalize gathers ONE line
__device__ uint4 g_sinv[MAXN];
// persisted exp(relu(logit)) per edge, fp16 x8 = 16B/edge, coalesced
__device__ ulonglong2 g_ex[MAXE];

// ---------------------------------------------------------------------------
// K1: setup — fold attn_l/attn_r into W_fc (blocks 0..255, one per input row i)
//     and build the TxH edge-type logit table (blocks 256..263, one per t).
// ---------------------------------------------------------------------------
__global__ void setup(const float* __restrict__ W_fc,
                      const float* __restrict__ attn_l,
                      const float* __restrict__ attn_r,
                      const float* __restrict__ edge_emb,
                      const float* __restrict__ W_e,
                      const float* __restrict__ attn_e) {
    int h = threadIdx.x >> 5;
    int lane = threadIdx.x & 31;
    if (blockIdx.x < IN_F) {
        int i = blockIdx.x;
        const float* wrow = W_fc + (size_t)i * (NHEAD * OUT_F) + h * OUT_F;
        const float* al = attn_l + h * OUT_F;
        const float* ar = attn_r + h * OUT_F;
        float sl = wrow[lane] * al[lane] + wrow[lane + 32] * al[lane + 32];
        float sr = wrow[lane] * ar[lane] + wrow[lane + 32] * ar[lane + 32];
#pragma unroll
        for (int o = 16; o; o >>= 1) {
            sl += __shfl_xor_sync(0xFFFFFFFFu, sl, o);
            sr += __shfl_xor_sync(0xFFFFFFFFu, sr, o);
        }
        if (lane == 0) {
            g_A[i * 16 + h] = sl;
            g_A[i * 16 + 8 + h] = sr;
        }
    } else {
        int t = blockIdx.x - IN_F;
        float acc = 0.0f;
#pragma unroll
        for (int j = 0; j < 2; j++) {
            int f = lane + j * 32;
            float proj = 0.0f;
#pragma unroll 8
            for (int g = 0; g < 64; g++)
                proj += edge_emb[t * 64 + g] * W_e[(size_t)g * (NHEAD * 64) + h * 64 + f];
            acc += proj * attn_e[h * 64 + f];
        }
#pragma unroll
        for (int o = 16; o; o >>= 1)
            acc += __shfl_xor_sync(0xFFFFFFFFu, acc, o);
        if (lane == 0) g_ee[t * NHEAD + h] = acc;
    }
}

// ---------------------------------------------------------------------------
// K2: node projection el/er = feat @ [A_l | A_r]   ([N,256] @ [256,16]).
// 2 nodes per thread; packed fma.rn.f32x2 (2 MACs per FMA slot). Stores fp16
// records; zeroes g_s4.
// ---------------------------------------------------------------------------
__global__ void __launch_bounds__(128) node_proj(const float* __restrict__ feat, int N) {
    __shared__ __align__(16) float sA[IN_F * 16];   // 16 KB
    __shared__ float sF[4][64][32];                 // 32 KB, XOR-swizzled
    int tid = threadIdx.x;
    for (int i = tid; i < IN_F * 16; i += 128) sA[i] = g_A[i];
    int w = tid >> 5, lane = tid & 31;
    int warpBase = blockIdx.x * 256 + w * 64;       // 64 nodes per warp
    ull acc0[8], acc1[8];
#pragma unroll
    for (int j = 0; j < 8; j++) { acc0[j] = 0ULL; acc1[j] = 0ULL; }
    __syncthreads();

    for (int kc = 0; kc < IN_F; kc += 32) {
#pragma unroll 16
        for (int r = 0; r < 64; r++) {
            int row = warpBase + r;
            if (row > N - 1) row = N - 1;
            sF[w][r][(lane + r) & 31] = __ldcs(&feat[(size_t)row * IN_F + kc + lane]);
        }
        __syncwarp();
#pragma unroll 8
        for (int k = 0; k < 32; k++) {
            int col = (k + lane) & 31;
            float f0 = sF[w][lane][col];
            float f1 = sF[w][lane + 32][col];
            ull fb0, fb1;
            asm("mov.b64 %0, {%1, %1};" : "=l"(fb0) : "f"(f0));
            asm("mov.b64 %0, {%1, %1};" : "=l"(fb1) : "f"(f1));
            const longlong2* ap = (const longlong2*)&sA[(kc + k) * 16];
            longlong2 q0 = ap[0], q1 = ap[1], q2 = ap[2], q3 = ap[3];
            asm("fma.rn.f32x2 %0, %1, %2, %0;" : "+l"(acc0[0]) : "l"(fb0), "l"((ull)q0.x));
            asm("fma.rn.f32x2 %0, %1, %2, %0;" : "+l"(acc0[1]) : "l"(fb0), "l"((ull)q0.y));
            asm("fma.rn.f32x2 %0, %1, %2, %0;" : "+l"(acc0[2]) : "l"(fb0), "l"((ull)q1.x));
            asm("fma.rn.f32x2 %0, %1, %2, %0;" : "+l"(acc0[3]) : "l"(fb0), "l"((ull)q1.y));
            asm("fma.rn.f32x2 %0, %1, %2, %0;" : "+l"(acc0[4]) : "l"(fb0), "l"((ull)q2.x));
            asm("fma.rn.f32x2 %0, %1, %2, %0;" : "+l"(acc0[5]) : "l"(fb0), "l"((ull)q2.y));
            asm("fma.rn.f32x2 %0, %1, %2, %0;" : "+l"(acc0[6]) : "l"(fb0), "l"((ull)q3.x));
            asm("fma.rn.f32x2 %0, %1, %2, %0;" : "+l"(acc0[7]) : "l"(fb0), "l"((ull)q3.y));
            asm("fma.rn.f32x2 %0, %1, %2, %0;" : "+l"(acc1[0]) : "l"(fb1), "l"((ull)q0.x));
            asm("fma.rn.f32x2 %0, %1, %2, %0;" : "+l"(acc1[1]) : "l"(fb1), "l"((ull)q0.y));
            asm("fma.rn.f32x2 %0, %1, %2, %0;" : "+l"(acc1[2]) : "l"(fb1), "l"((ull)q1.x));
            asm("fma.rn.f32x2 %0, %1, %2, %0;" : "+l"(acc1[3]) : "l"(fb1), "l"((ull)q1.y));
            asm("fma.rn.f32x2 %0, %1, %2, %0;" : "+l"(acc1[4]) : "l"(fb1), "l"((ull)q2.x));
            asm("fma.rn.f32x2 %0, %1, %2, %0;" : "+l"(acc1[5]) : "l"(fb1), "l"((ull)q2.y));
            asm("fma.rn.f32x2 %0, %1, %2, %0;" : "+l"(acc1[6]) : "l"(fb1), "l"((ull)q3.x));
            asm("fma.rn.f32x2 %0, %1, %2, %0;" : "+l"(acc1[7]) : "l"(fb1), "l"((ull)q3.y));
        }
        __syncwarp();
    }
#pragma unroll
    for (int nn = 0; nn < 2; nn++) {
        int myNode = warpBase + lane + nn * 32;
        ull* acc = nn ? acc1 : acc0;
        if (myNode < N) {
            float v[16];
#pragma unroll
            for (int j = 0; j < 8; j++)
                asm("mov.b64 {%0, %1}, %2;" : "=f"(v[2 * j]), "=f"(v[2 * j + 1]) : "l"(acc[j]));
            __half2 l01 = __floats2half2_rn(v[0], v[1]);
            __half2 l23 = __floats2half2_rn(v[2], v[3]);
            __half2 l45 = __floats2half2_rn(v[4], v[5]);
            __half2 l67 = __floats2half2_rn(v[6], v[7]);
            uint4 u;
            u.x = *(unsigned*)&l01; u.y = *(unsigned*)&l23;
            u.z = *(unsigned*)&l45; u.w = *(unsigned*)&l67;
            g_elh[myNode] = u;
            __half2 r01 = __floats2half2_rn(v[8], v[9]);
            __half2 r23 = __floats2half2_rn(v[10], v[11]);
            __half2 r45 = __floats2half2_rn(v[12], v[13]);
            __half2 r67 = __floats2half2_rn(v[14], v[15]);
            uint4 q;
            q.x = *(unsigned*)&r01; q.y = *(unsigned*)&r23;
            q.z = *(unsigned*)&r45; q.w = *(unsigned*)&r67;
            g_erh[myNode] = q;
            float4 z = make_float4(0.f, 0.f, 0.f, 0.f);
            g_s4[(size_t)myNode * 2]     = z;
            g_s4[(size_t)myNode * 2 + 1] = z;
        }
    }
}

// ---------------------------------------------------------------------------
// K3 edge body: 2 gather LDG.128 results -> exp -> 2x red.v4 -> fp16 ex store.
// Max-shift dropped (softmax shift-invariant; logits in [0,~0.8]).
// ---------------------------------------------------------------------------
__device__ __forceinline__ void expsum_body(int e, uint4 lu, uint4 ru, int t, int d,
                                            const float* see) {
    float2 l0 = __half22float2(*(__half2*)&lu.x);
    float2 l1 = __half22float2(*(__half2*)&lu.y);
    float2 l2 = __half22float2(*(__half2*)&lu.z);
    float2 l3 = __half22float2(*(__half2*)&lu.w);
    float2 r0 = __half22float2(*(__half2*)&ru.x);
    float2 r1 = __half22float2(*(__half2*)&ru.y);
    float2 r2 = __half22float2(*(__half2*)&ru.z);
    float2 r3 = __half22float2(*(__half2*)&ru.w);
    float4 b0 = *(const float4*)(see + t * 8);
    float4 b1 = *(const float4*)(see + t * 8 + 4);
    float x0 = __expf(fmaxf(l0.x + r0.x + b0.x, 0.0f));
    float x1 = __expf(fmaxf(l0.y + r0.y + b0.y, 0.0f));
    float x2 = __expf(fmaxf(l1.x + r1.x + b0.z, 0.0f));
    float x3 = __expf(fmaxf(l1.y + r1.y + b0.w, 0.0f));
    float x4 = __expf(fmaxf(l2.x + r2.x + b1.x, 0.0f));
    float x5 = __expf(fmaxf(l2.y + r2.y + b1.y, 0.0f));
    float x6 = __expf(fmaxf(l3.x + r3.x + b1.z, 0.0f));
    float x7 = __expf(fmaxf(l3.y + r3.y + b1.w, 0.0f));
    float* sp = (float*)&g_s4[(size_t)d * 2];
    asm volatile("red.global.add.v4.f32 [%0], {%1,%2,%3,%4};"
                 :: "l"(sp), "f"(x0), "f"(x1), "f"(x2), "f"(x3) : "memory");
    asm volatile("red.global.add.v4.f32 [%0], {%1,%2,%3,%4};"
                 :: "l"(sp + 4), "f"(x4), "f"(x5), "f"(x6), "f"(x7) : "memory");
    __half2 h01 = __floats2half2_rn(x0, x1);
    __half2 h23 = __floats2half2_rn(x2, x3);
    __half2 h45 = __floats2half2_rn(x4, x5);
    __half2 h67 = __floats2half2_rn(x6, x7);
    ulonglong2 packed;
    asm("mov.b64 %0, {%1, %2};" : "=l"(packed.x)
        : "r"(*(unsigned*)&h01), "r"(*(unsigned*)&h23));
    asm("mov.b64 %0, {%1, %2};" : "=l"(packed.y)
        : "r"(*(unsigned*)&h45), "r"(*(unsigned*)&h67));
    __stcs(&g_ex[e], packed);
}

// K3: 2 edges/thread via a BLOCK-UNIFORM full-tile fast path (no per-edge
// predication, no divergence — E=3.2M is tile-divisible so all blocks take
// it). Index loads + all 4 gathers front-batched: MLP doubles vs R12.
__global__ void __launch_bounds__(256) edge_expsum(const int* __restrict__ et,
                                                   const int* __restrict__ src,
                                                   const int* __restrict__ dst,
                                                   int E) {
    __shared__ __align__(16) float see[TMAX * NHEAD];
    if (threadIdx.x < TMAX * NHEAD) see[threadIdx.x] = g_ee[threadIdx.x];
    __syncthreads();
    int base = blockIdx.x * 512;
    if (base + 512 <= E) {                       // uniform across block
        int e0 = base + threadIdx.x;
        int e1 = e0 + 256;
        int s0 = __ldcs(&src[e0]);
        int d0 = __ldcs(&dst[e0]);
        int t0 = __ldcs(&et[e0]);
        int s1 = __ldcs(&src[e1]);
        int d1 = __ldcs(&dst[e1]);
        int t1 = __ldcs(&et[e1]);
        uint4 lu0 = __ldg(&g_elh[s0]);
        uint4 ru0 = __ldg(&g_erh[d0]);
        uint4 lu1 = __ldg(&g_elh[s1]);
        uint4 ru1 = __ldg(&g_erh[d1]);
        expsum_body(e0, lu0, ru0, t0, d0, see);
        expsum_body(e1, lu1, ru1, t1, d1, see);
    } else {
        for (int e = base + threadIdx.x; e < E; e += 256) {
            int s = __ldcs(&src[e]);
            int d = __ldcs(&dst[e]);
            int t = __ldcs(&et[e]);
            uint4 lu = __ldg(&g_elh[s]);
            uint4 ru = __ldg(&g_erh[d]);
            expsum_body(e, lu, ru, t, d, see);
        }
    }
}

// ---------------------------------------------------------------------------
// K4: pack 1/s into fp16x8 (16B/node) so finalize gathers ONE line per edge.
// ---------------------------------------------------------------------------
__global__ void recip_pack(int N) {
    int i = blockIdx.x * 256 + threadIdx.x;
    if (i >= N) return;
    float4 s0 = g_s4[(size_t)i * 2];
    float4 s1 = g_s4[(size_t)i * 2 + 1];
    __half2 a = __floats2half2_rn(__fdividef(1.f, s0.x), __fdividef(1.f, s0.y));
    __half2 b = __floats2half2_rn(__fdividef(1.f, s0.z), __fdividef(1.f, s0.w));
    __half2 c = __floats2half2_rn(__fdividef(1.f, s1.x), __fdividef(1.f, s1.y));
    __half2 d = __floats2half2_rn(__fdividef(1.f, s1.z), __fdividef(1.f, s1.w));
    uint4 u;
    u.x = *(unsigned*)&a; u.y = *(unsigned*)&b;
    u.z = *(unsigned*)&c; u.w = *(unsigned*)&d;
    g_sinv[i] = u;
}

// ---------------------------------------------------------------------------
// K5 (finalize): out = ex * sinv[dst].
// ---------------------------------------------------------------------------
__device__ __forceinline__ void fin_body(int e, ulonglong2 p, uint4 si,
                                         float* __restrict__ out) {
    unsigned a0, a1, a2, a3;
    asm("mov.b64 {%0, %1}, %2;" : "=r"(a0), "=r"(a1) : "l"(p.x));
    asm("mov.b64 {%0, %1}, %2;" : "=r"(a2), "=r"(a3) : "l"(p.y));
    float2 x01 = __half22float2(*(__half2*)&a0);
    float2 x23 = __half22float2(*(__half2*)&a1);
    float2 x45 = __half22float2(*(__half2*)&a2);
    float2 x67 = __half22float2(*(__half2*)&a3);
    float2 i01 = __half22float2(*(__half2*)&si.x);
    float2 i23 = __half22float2(*(__half2*)&si.y);
    float2 i45 = __half22float2(*(__half2*)&si.z);
    float2 i67 = __half22float2(*(__half2*)&si.w);
    float4 o0, o1;
    o0.x = x01.x * i01.x;
    o0.y = x01.y * i01.y;
    o0.z = x23.x * i23.x;
    o0.w = x23.y * i23.y;
    o1.x = x45.x * i45.x;
    o1.y = x45.y * i45.y;
    o1.z = x67.x * i67.x;
    o1.w = x67.y * i67.y;
    __stcs((float4*)(out + (size_t)e * 8), o0);
    __stcs((float4*)(out + (size_t)e * 8) + 1, o1);
}

// 4 edges/thread, block-uniform full-tile fast path (tile = 1024 edges).
__global__ void __launch_bounds__(256) finalize(const int* __restrict__ dst,
                                                float* __restrict__ out,
                                                int E) {
    int base = blockIdx.x * 1024;
    if (base + 1024 <= E) {                      // uniform across block
        int e0 = base + threadIdx.x;
        int d0 = __ldcs(&dst[e0]);
        int d1 = __ldcs(&dst[e0 + 256]);
        int d2 = __ldcs(&dst[e0 + 512]);
        int d3 = __ldcs(&dst[e0 + 768]);
        ulonglong2 p0 = __ldcs(&g_ex[e0]);
        ulonglong2 p1 = __ldcs(&g_ex[e0 + 256]);
        ulonglong2 p2 = __ldcs(&g_ex[e0 + 512]);
        ulonglong2 p3 = __ldcs(&g_ex[e0 + 768]);
        uint4 si0 = __ldg(&g_sinv[d0]);
        uint4 si1 = __ldg(&g_sinv[d1]);
        uint4 si2 = __ldg(&g_sinv[d2]);
        uint4 si3 = __ldg(&g_sinv[d3]);
        fin_body(e0,       p0, si0, out);
        fin_body(e0 + 256, p1, si1, out);
        fin_body(e0 + 512, p2, si2, out);
        fin_body(e0 + 768, p3, si3, out);
    } else {
        for (int e = base + threadIdx.x; e < E; e += 256) {
            int d = __ldcs(&dst[e]);
            ulonglong2 p = __ldcs(&g_ex[e]);
            uint4 si = __ldg(&g_sinv[d]);
            fin_body(e, p, si, out);
        }
    }
}

// ---------------------------------------------------------------------------
extern "C" void kernel_launch(void* const* d_in, const int* in_sizes, int n_in,
                              void* d_out, int out_size) {
    const float* feat     = (const float*)d_in[0];
    const int*   etype    = (const int*)  d_in[1];
    const int*   src      = (const int*)  d_in[2];
    const int*   dst      = (const int*)  d_in[3];
    const float* W_fc     = (const float*)d_in[4];
    const float* edge_emb = (const float*)d_in[5];
    const float* W_e      = (const float*)d_in[6];
    const float* attn_l   = (const float*)d_in[7];
    const float* attn_r   = (const float*)d_in[8];
    const float* attn_e   = (const float*)d_in[9];
    float* out = (float*)d_out;

    int N = in_sizes[0] / IN_F;
    int E = in_sizes[1];

    setup<<<IN_F + TMAX, 256>>>(W_fc, attn_l, attn_r, edge_emb, W_e, attn_e);
    node_proj<<<(N + 255) / 256, 128>>>(feat, N);
    edge_expsum<<<(E + 511) / 512, 256>>>(etype, src, dst, E);
    recip_pack<<<(N + 255) / 256, 256>>>(N);
    finalize<<<(E + 1023) / 1024, 256>>>(dst, out, E);
}

// round 14
// speedup vs baseline: 1.0460x; 1.0460x over previous
#include <cuda_runtime.h>
#include <cuda_fp16.h>

#define IN_F 256
#define NHEAD 8
#define OUT_F 64
#define TMAX 8
#define MAXN 100000
#define MAXE 3200000

typedef unsigned long long ull;

// Scratch (static __device__ — no allocations allowed)
__device__ float g_A[IN_F * 16];        // [i][0..7]=A_l, [i][8..15]=A_r
__device__ float g_ee[TMAX * NHEAD];    // per-etype logit table
// el/er as fp16: one 16B record per node (8 halfs), single LDG.128 gather
__device__ uint4 g_elh[MAXN];
__device__ uint4 g_erh[MAXN];
// softmax denominator, fp32 (atomic target), 32B per node record
__device__ float4 g_s4[MAXN * 2];
// 1/s packed fp16x8: one 16B record per node -> finalize gathers ONE line
__device__ uint4 g_sinv[MAXN];
// persisted exp(relu(logit)) per edge, fp16 x8 = 16B/edge, coalesced.
// Written by expsum, re-read by finalize: default (write-back, LRU) policy so
// it stays L2-resident between the two kernels (L2=126MB persists across
// launches; only L1D flushes).
__device__ ulonglong2 g_ex[MAXE];

// ---------------------------------------------------------------------------
// K1: setup — fold attn_l/attn_r into W_fc (blocks 0..255, one per input row i)
//     and build the TxH edge-type logit table (blocks 256..263, one per t).
// ---------------------------------------------------------------------------
__global__ void setup(const float* __restrict__ W_fc,
                      const float* __restrict__ attn_l,
                      const float* __restrict__ attn_r,
                      const float* __restrict__ edge_emb,
                      const float* __restrict__ W_e,
                      const float* __restrict__ attn_e) {
    int h = threadIdx.x >> 5;
    int lane = threadIdx.x & 31;
    if (blockIdx.x < IN_F) {
        int i = blockIdx.x;
        const float* wrow = W_fc + (size_t)i * (NHEAD * OUT_F) + h * OUT_F;
        const float* al = attn_l + h * OUT_F;
        const float* ar = attn_r + h * OUT_F;
        float sl = wrow[lane] * al[lane] + wrow[lane + 32] * al[lane + 32];
        float sr = wrow[lane] * ar[lane] + wrow[lane + 32] * ar[lane + 32];
#pragma unroll
        for (int o = 16; o; o >>= 1) {
            sl += __shfl_xor_sync(0xFFFFFFFFu, sl, o);
            sr += __shfl_xor_sync(0xFFFFFFFFu, sr, o);
        }
        if (lane == 0) {
            g_A[i * 16 + h] = sl;
            g_A[i * 16 + 8 + h] = sr;
        }
    } else {
        int t = blockIdx.x - IN_F;
        float acc = 0.0f;
#pragma unroll
        for (int j = 0; j < 2; j++) {
            int f = lane + j * 32;
            float proj = 0.0f;
#pragma unroll 8
            for (int g = 0; g < 64; g++)
                proj += edge_emb[t * 64 + g] * W_e[(size_t)g * (NHEAD * 64) + h * 64 + f];
            acc += proj * attn_e[h * 64 + f];
        }
#pragma unroll
        for (int o = 16; o; o >>= 1)
            acc += __shfl_xor_sync(0xFFFFFFFFu, acc, o);
        if (lane == 0) g_ee[t * NHEAD + h] = acc;
    }
}

// ---------------------------------------------------------------------------
// K2: node projection el/er = feat @ [A_l | A_r]   ([N,256] @ [256,16]).
// 2 nodes per thread; packed fma.rn.f32x2 (2 MACs per FMA slot). Stores fp16
// records; zeroes g_s4.
// ---------------------------------------------------------------------------
__global__ void __launch_bounds__(128) node_proj(const float* __restrict__ feat, int N) {
    __shared__ __align__(16) float sA[IN_F * 16];   // 16 KB
    __shared__ float sF[4][64][32];                 // 32 KB, XOR-swizzled
    int tid = threadIdx.x;
    for (int i = tid; i < IN_F * 16; i += 128) sA[i] = g_A[i];
    int w = tid >> 5, lane = tid & 31;
    int warpBase = blockIdx.x * 256 + w * 64;       // 64 nodes per warp
    ull acc0[8], acc1[8];
#pragma unroll
    for (int j = 0; j < 8; j++) { acc0[j] = 0ULL; acc1[j] = 0ULL; }
    __syncthreads();

    for (int kc = 0; kc < IN_F; kc += 32) {
#pragma unroll 16
        for (int r = 0; r < 64; r++) {
            int row = warpBase + r;
            if (row > N - 1) row = N - 1;
            sF[w][r][(lane + r) & 31] = __ldcs(&feat[(size_t)row * IN_F + kc + lane]);
        }
        __syncwarp();
#pragma unroll 8
        for (int k = 0; k < 32; k++) {
            int col = (k + lane) & 31;
            float f0 = sF[w][lane][col];
            float f1 = sF[w][lane + 32][col];
            ull fb0, fb1;
            asm("mov.b64 %0, {%1, %1};" : "=l"(fb0) : "f"(f0));
            asm("mov.b64 %0, {%1, %1};" : "=l"(fb1) : "f"(f1));
            const longlong2* ap = (const longlong2*)&sA[(kc + k) * 16];
            longlong2 q0 = ap[0], q1 = ap[1], q2 = ap[2], q3 = ap[3];
            asm("fma.rn.f32x2 %0, %1, %2, %0;" : "+l"(acc0[0]) : "l"(fb0), "l"((ull)q0.x));
            asm("fma.rn.f32x2 %0, %1, %2, %0;" : "+l"(acc0[1]) : "l"(fb0), "l"((ull)q0.y));
            asm("fma.rn.f32x2 %0, %1, %2, %0;" : "+l"(acc0[2]) : "l"(fb0), "l"((ull)q1.x));
            asm("fma.rn.f32x2 %0, %1, %2, %0;" : "+l"(acc0[3]) : "l"(fb0), "l"((ull)q1.y));
            asm("fma.rn.f32x2 %0, %1, %2, %0;" : "+l"(acc0[4]) : "l"(fb0), "l"((ull)q2.x));
            asm("fma.rn.f32x2 %0, %1, %2, %0;" : "+l"(acc0[5]) : "l"(fb0), "l"((ull)q2.y));
            asm("fma.rn.f32x2 %0, %1, %2, %0;" : "+l"(acc0[6]) : "l"(fb0), "l"((ull)q3.x));
            asm("fma.rn.f32x2 %0, %1, %2, %0;" : "+l"(acc0[7]) : "l"(fb0), "l"((ull)q3.y));
            asm("fma.rn.f32x2 %0, %1, %2, %0;" : "+l"(acc1[0]) : "l"(fb1), "l"((ull)q0.x));
            asm("fma.rn.f32x2 %0, %1, %2, %0;" : "+l"(acc1[1]) : "l"(fb1), "l"((ull)q0.y));
            asm("fma.rn.f32x2 %0, %1, %2, %0;" : "+l"(acc1[2]) : "l"(fb1), "l"((ull)q1.x));
            asm("fma.rn.f32x2 %0, %1, %2, %0;" : "+l"(acc1[3]) : "l"(fb1), "l"((ull)q1.y));
            asm("fma.rn.f32x2 %0, %1, %2, %0;" : "+l"(acc1[4]) : "l"(fb1), "l"((ull)q2.x));
            asm("fma.rn.f32x2 %0, %1, %2, %0;" : "+l"(acc1[5]) : "l"(fb1), "l"((ull)q2.y));
            asm("fma.rn.f32x2 %0, %1, %2, %0;" : "+l"(acc1[6]) : "l"(fb1), "l"((ull)q3.x));
            asm("fma.rn.f32x2 %0, %1, %2, %0;" : "+l"(acc1[7]) : "l"(fb1), "l"((ull)q3.y));
        }
        __syncwarp();
    }
#pragma unroll
    for (int nn = 0; nn < 2; nn++) {
        int myNode = warpBase + lane + nn * 32;
        ull* acc = nn ? acc1 : acc0;
        if (myNode < N) {
            float v[16];
#pragma unroll
            for (int j = 0; j < 8; j++)
                asm("mov.b64 {%0, %1}, %2;" : "=f"(v[2 * j]), "=f"(v[2 * j + 1]) : "l"(acc[j]));
            __half2 l01 = __floats2half2_rn(v[0], v[1]);
            __half2 l23 = __floats2half2_rn(v[2], v[3]);
            __half2 l45 = __floats2half2_rn(v[4], v[5]);
            __half2 l67 = __floats2half2_rn(v[6], v[7]);
            uint4 u;
            u.x = *(unsigned*)&l01; u.y = *(unsigned*)&l23;
            u.z = *(unsigned*)&l45; u.w = *(unsigned*)&l67;
            g_elh[myNode] = u;
            __half2 r01 = __floats2half2_rn(v[8], v[9]);
            __half2 r23 = __floats2half2_rn(v[10], v[11]);
            __half2 r45 = __floats2half2_rn(v[12], v[13]);
            __half2 r67 = __floats2half2_rn(v[14], v[15]);
            uint4 q;
            q.x = *(unsigned*)&r01; q.y = *(unsigned*)&r23;
            q.z = *(unsigned*)&r45; q.w = *(unsigned*)&r67;
            g_erh[myNode] = q;
            float4 z = make_float4(0.f, 0.f, 0.f, 0.f);
            g_s4[(size_t)myNode * 2]     = z;
            g_s4[(size_t)myNode * 2 + 1] = z;
        }
    }
}

// ---------------------------------------------------------------------------
// K3: 1 thread per edge, all 8 heads (clean R12 form). Per edge: 2 gather
// LDG.128 (L2-resident tables), 2x red.global.add.v4, 1 coalesced STG.128 of
// fp16 ex (DEFAULT policy -> stays in L2 for finalize). et/src are read-once
// (.cs); dst is re-read by finalize (default policy). Max-shift dropped
// (softmax shift-invariant; logits in [0,~0.8]).
// ---------------------------------------------------------------------------
__global__ void __launch_bounds__(256) edge_expsum(const int* __restrict__ et,
                                                   const int* __restrict__ src,
                                                   const int* __restrict__ dst,
                                                   int E) {
    __shared__ __align__(16) float see[TMAX * NHEAD];
    if (threadIdx.x < TMAX * NHEAD) see[threadIdx.x] = g_ee[threadIdx.x];
    __syncthreads();
    int e = blockIdx.x * 256 + threadIdx.x;
    if (e >= E) return;
    int s = __ldcs(&src[e]);
    int d = dst[e];                      // default: keep L2-resident for finalize
    int t = __ldcs(&et[e]);
    uint4 lu = __ldg(&g_elh[s]);
    uint4 ru = __ldg(&g_erh[d]);
    float2 l0 = __half22float2(*(__half2*)&lu.x);
    float2 l1 = __half22float2(*(__half2*)&lu.y);
    float2 l2 = __half22float2(*(__half2*)&lu.z);
    float2 l3 = __half22float2(*(__half2*)&lu.w);
    float2 r0 = __half22float2(*(__half2*)&ru.x);
    float2 r1 = __half22float2(*(__half2*)&ru.y);
    float2 r2 = __half22float2(*(__half2*)&ru.z);
    float2 r3 = __half22float2(*(__half2*)&ru.w);
    float4 b0 = *(const float4*)(see + t * 8);
    float4 b1 = *(const float4*)(see + t * 8 + 4);
    float x0 = __expf(fmaxf(l0.x + r0.x + b0.x, 0.0f));
    float x1 = __expf(fmaxf(l0.y + r0.y + b0.y, 0.0f));
    float x2 = __expf(fmaxf(l1.x + r1.x + b0.z, 0.0f));
    float x3 = __expf(fmaxf(l1.y + r1.y + b0.w, 0.0f));
    float x4 = __expf(fmaxf(l2.x + r2.x + b1.x, 0.0f));
    float x5 = __expf(fmaxf(l2.y + r2.y + b1.y, 0.0f));
    float x6 = __expf(fmaxf(l3.x + r3.x + b1.z, 0.0f));
    float x7 = __expf(fmaxf(l3.y + r3.y + b1.w, 0.0f));
    float* sp = (float*)&g_s4[(size_t)d * 2];
    asm volatile("red.global.add.v4.f32 [%0], {%1,%2,%3,%4};"
                 :: "l"(sp), "f"(x0), "f"(x1), "f"(x2), "f"(x3) : "memory");
    asm volatile("red.global.add.v4.f32 [%0], {%1,%2,%3,%4};"
                 :: "l"(sp + 4), "f"(x4), "f"(x5), "f"(x6), "f"(x7) : "memory");
    __half2 h01 = __floats2half2_rn(x0, x1);
    __half2 h23 = __floats2half2_rn(x2, x3);
    __half2 h45 = __floats2half2_rn(x4, x5);
    __half2 h67 = __floats2half2_rn(x6, x7);
    ulonglong2 packed;
    asm("mov.b64 %0, {%1, %2};" : "=l"(packed.x)
        : "r"(*(unsigned*)&h01), "r"(*(unsigned*)&h23));
    asm("mov.b64 %0, {%1, %2};" : "=l"(packed.y)
        : "r"(*(unsigned*)&h45), "r"(*(unsigned*)&h67));
    g_ex[e] = packed;                    // default write-back: L2-resident
}

// ---------------------------------------------------------------------------
// K4: pack 1/s into fp16x8 (16B/node) so finalize gathers ONE line per edge.
// ---------------------------------------------------------------------------
__global__ void recip_pack(int N) {
    int i = blockIdx.x * 512 + threadIdx.x;
    if (i >= N) return;
    float4 s0 = g_s4[(size_t)i * 2];
    float4 s1 = g_s4[(size_t)i * 2 + 1];
    __half2 a = __floats2half2_rn(__fdividef(1.f, s0.x), __fdividef(1.f, s0.y));
    __half2 b = __floats2half2_rn(__fdividef(1.f, s0.z), __fdividef(1.f, s0.w));
    __half2 c = __floats2half2_rn(__fdividef(1.f, s1.x), __fdividef(1.f, s1.y));
    __half2 d = __floats2half2_rn(__fdividef(1.f, s1.z), __fdividef(1.f, s1.w));
    uint4 u;
    u.x = *(unsigned*)&a; u.y = *(unsigned*)&b;
    u.z = *(unsigned*)&c; u.w = *(unsigned*)&d;
    g_sinv[i] = u;
}

// ---------------------------------------------------------------------------
// K5 (finalize): out = ex * sinv[dst]. 1 thread/edge: dst 4B (L2 hit) + ex
// LDG.128 (L2 hit) + ONE scattered LDG.128 (sinv) + 2 streaming STG.128
// (out is write-once: .cs keeps it from evicting the resident data).
// ---------------------------------------------------------------------------
__global__ void __launch_bounds__(256) finalize(const int* __restrict__ dst,
                                                float* __restrict__ out,
                                                int E) {
    int e = blockIdx.x * 256 + threadIdx.x;
    if (e >= E) return;
    int d = dst[e];
    ulonglong2 p = g_ex[e];
    uint4 si = __ldg(&g_sinv[d]);
    unsigned a0, a1, a2, a3;
    asm("mov.b64 {%0, %1}, %2;" : "=r"(a0), "=r"(a1) : "l"(p.x));
    asm("mov.b64 {%0, %1}, %2;" : "=r"(a2), "=r"(a3) : "l"(p.y));
    float2 x01 = __half22float2(*(__half2*)&a0);
    float2 x23 = __half22float2(*(__half2*)&a1);
    float2 x45 = __half22float2(*(__half2*)&a2);
    float2 x67 = __half22float2(*(__half2*)&a3);
    float2 i01 = __half22float2(*(__half2*)&si.x);
    float2 i23 = __half22float2(*(__half2*)&si.y);
    float2 i45 = __half22float2(*(__half2*)&si.z);
    float2 i67 = __half22float2(*(__half2*)&si.w);
    float4 o0, o1;
    o0.x = x01.x * i01.x;
    o0.y = x01.y * i01.y;
    o0.z = x23.x * i23.x;
    o0.w = x23.y * i23.y;
    o1.x = x45.x * i45.x;
    o1.y = x45.y * i45.y;
    o1.z = x67.x * i67.x;
    o1.w = x67.y * i67.y;
    __stcs((float4*)(out + (size_t)e * 8), o0);
    __stcs((float4*)(out + (size_t)e * 8) + 1, o1);
}

// ---------------------------------------------------------------------------
extern "C" void kernel_launch(void* const* d_in, const int* in_sizes, int n_in,
                              void* d_out, int out_size) {
    const float* feat     = (const float*)d_in[0];
    const int*   etype    = (const int*)  d_in[1];
    const int*   src      = (const int*)  d_in[2];
    const int*   dst      = (const int*)  d_in[3];
    const float* W_fc     = (const float*)d_in[4];
    const float* edge_emb = (const float*)d_in[5];
    const float* W_e      = (const float*)d_in[6];
    const float* attn_l   = (const float*)d_in[7];
    const float* attn_r   = (const float*)d_in[8];
    const float* attn_e   = (const float*)d_in[9];
    float* out = (float*)d_out;

    int N = in_sizes[0] / IN_F;
    int E = in_sizes[1];

    setup<<<IN_F + TMAX, 256>>>(W_fc, attn_l, attn_r, edge_emb, W_e, attn_e);
    node_proj<<<(N + 255) / 256, 128>>>(feat, N);
    edge_expsum<<<(E + 255) / 256, 256>>>(etype, src, dst, E);
    recip_pack<<<(N + 511) / 512, 512>>>(N);
    finalize<<<(E + 255) / 256, 256>>>(dst, out, E);
}

// round 15
// speedup vs baseline: 1.0529x; 1.0066x over previous
#include <cuda_runtime.h>
#include <cuda_fp16.h>

#define IN_F 256
#define NHEAD 8
#define OUT_F 64
#define TMAX 8
#define MAXN 100000
#define MAXE 3200000
#define LOG2E 1.4426950408889634f

typedef unsigned long long ull;

// Scratch (static __device__ — no allocations allowed)
// NOTE: A and ee are PRESCALED by log2e, so exp(relu(x)) == 2^max(x',0).
__device__ float g_A[IN_F * 16];        // [i][0..7]=A_l, [i][8..15]=A_r (×log2e)
__device__ float g_ee[TMAX * NHEAD];    // per-etype logit table (×log2e)
// el/er as fp16 (scaled domain): one 16B record per node, single LDG.128 gather
__device__ uint4 g_elh[MAXN];
__device__ uint4 g_erh[MAXN];
// softmax denominator, fp32 (atomic target), 32B per node record
__device__ float4 g_s4[MAXN * 2];
// 1/s packed fp16x8: one 16B record per node -> finalize gathers ONE line
__device__ uint4 g_sinv[MAXN];
// persisted exp(relu(logit)) per edge, fp16 x8 = 16B/edge, coalesced
__device__ ulonglong2 g_ex[MAXE];

// ---------------------------------------------------------------------------
// K1: setup — fold attn_l/attn_r into W_fc (blocks 0..255, one per input row i)
//     and build the TxH edge-type logit table (blocks 256..263, one per t).
//     Both outputs are prescaled by log2e.
// ---------------------------------------------------------------------------
__global__ void setup(const float* __restrict__ W_fc,
                      const float* __restrict__ attn_l,
                      const float* __restrict__ attn_r,
                      const float* __restrict__ edge_emb,
                      const float* __restrict__ W_e,
                      const float* __restrict__ attn_e) {
    int h = threadIdx.x >> 5;
    int lane = threadIdx.x & 31;
    if (blockIdx.x < IN_F) {
        int i = blockIdx.x;
        const float* wrow = W_fc + (size_t)i * (NHEAD * OUT_F) + h * OUT_F;
        const float* al = attn_l + h * OUT_F;
        const float* ar = attn_r + h * OUT_F;
        float sl = wrow[lane] * al[lane] + wrow[lane + 32] * al[lane + 32];
        float sr = wrow[lane] * ar[lane] + wrow[lane + 32] * ar[lane + 32];
#pragma unroll
        for (int o = 16; o; o >>= 1) {
            sl += __shfl_xor_sync(0xFFFFFFFFu, sl, o);
            sr += __shfl_xor_sync(0xFFFFFFFFu, sr, o);
        }
        if (lane == 0) {
            g_A[i * 16 + h] = sl * LOG2E;
            g_A[i * 16 + 8 + h] = sr * LOG2E;
        }
    } else {
        int t = blockIdx.x - IN_F;
        float acc = 0.0f;
#pragma unroll
        for (int j = 0; j < 2; j++) {
            int f = lane + j * 32;
            float proj = 0.0f;
#pragma unroll 8
            for (int g = 0; g < 64; g++)
                proj += edge_emb[t * 64 + g] * W_e[(size_t)g * (NHEAD * 64) + h * 64 + f];
            acc += proj * attn_e[h * 64 + f];
        }
#pragma unroll
        for (int o = 16; o; o >>= 1)
            acc += __shfl_xor_sync(0xFFFFFFFFu, acc, o);
        if (lane == 0) g_ee[t * NHEAD + h] = acc * LOG2E;
    }
}

// ---------------------------------------------------------------------------
// K2: node projection el/er = feat @ [A_l | A_r]   ([N,256] @ [256,16]).
// 2 nodes per thread; packed fma.rn.f32x2 (2 MACs per FMA slot). Stores fp16
// records (scaled domain); zeroes g_s4.
// ---------------------------------------------------------------------------
__global__ void __launch_bounds__(128) node_proj(const float* __restrict__ feat, int N) {
    __shared__ __align__(16) float sA[IN_F * 16];   // 16 KB
    __shared__ float sF[4][64][32];                 // 32 KB, XOR-swizzled
    int tid = threadIdx.x;
    for (int i = tid; i < IN_F * 16; i += 128) sA[i] = g_A[i];
    int w = tid >> 5, lane = tid & 31;
    int warpBase = blockIdx.x * 256 + w * 64;       // 64 nodes per warp
    ull acc0[8], acc1[8];
#pragma unroll
    for (int j = 0; j < 8; j++) { acc0[j] = 0ULL; acc1[j] = 0ULL; }
    __syncthreads();

    for (int kc = 0; kc < IN_F; kc += 32) {
#pragma unroll 16
        for (int r = 0; r < 64; r++) {
            int row = warpBase + r;
            if (row > N - 1) row = N - 1;
            sF[w][r][(lane + r) & 31] = __ldcs(&feat[(size_t)row * IN_F + kc + lane]);
        }
        __syncwarp();
#pragma unroll 8
        for (int k = 0; k < 32; k++) {
            int col = (k + lane) & 31;
            float f0 = sF[w][lane][col];
            float f1 = sF[w][lane + 32][col];
            ull fb0, fb1;
            asm("mov.b64 %0, {%1, %1};" : "=l"(fb0) : "f"(f0));
            asm("mov.b64 %0, {%1, %1};" : "=l"(fb1) : "f"(f1));
            const longlong2* ap = (const longlong2*)&sA[(kc + k) * 16];
            longlong2 q0 = ap[0], q1 = ap[1], q2 = ap[2], q3 = ap[3];
            asm("fma.rn.f32x2 %0, %1, %2, %0;" : "+l"(acc0[0]) : "l"(fb0), "l"((ull)q0.x));
            asm("fma.rn.f32x2 %0, %1, %2, %0;" : "+l"(acc0[1]) : "l"(fb0), "l"((ull)q0.y));
            asm("fma.rn.f32x2 %0, %1, %2, %0;" : "+l"(acc0[2]) : "l"(fb0), "l"((ull)q1.x));
            asm("fma.rn.f32x2 %0, %1, %2, %0;" : "+l"(acc0[3]) : "l"(fb0), "l"((ull)q1.y));
            asm("fma.rn.f32x2 %0, %1, %2, %0;" : "+l"(acc0[4]) : "l"(fb0), "l"((ull)q2.x));
            asm("fma.rn.f32x2 %0, %1, %2, %0;" : "+l"(acc0[5]) : "l"(fb0), "l"((ull)q2.y));
            asm("fma.rn.f32x2 %0, %1, %2, %0;" : "+l"(acc0[6]) : "l"(fb0), "l"((ull)q3.x));
            asm("fma.rn.f32x2 %0, %1, %2, %0;" : "+l"(acc0[7]) : "l"(fb0), "l"((ull)q3.y));
            asm("fma.rn.f32x2 %0, %1, %2, %0;" : "+l"(acc1[0]) : "l"(fb1), "l"((ull)q0.x));
            asm("fma.rn.f32x2 %0, %1, %2, %0;" : "+l"(acc1[1]) : "l"(fb1), "l"((ull)q0.y));
            asm("fma.rn.f32x2 %0, %1, %2, %0;" : "+l"(acc1[2]) : "l"(fb1), "l"((ull)q1.x));
            asm("fma.rn.f32x2 %0, %1, %2, %0;" : "+l"(acc1[3]) : "l"(fb1), "l"((ull)q1.y));
            asm("fma.rn.f32x2 %0, %1, %2, %0;" : "+l"(acc1[4]) : "l"(fb1), "l"((ull)q2.x));
            asm("fma.rn.f32x2 %0, %1, %2, %0;" : "+l"(acc1[5]) : "l"(fb1), "l"((ull)q2.y));
            asm("fma.rn.f32x2 %0, %1, %2, %0;" : "+l"(acc1[6]) : "l"(fb1), "l"((ull)q3.x));
            asm("fma.rn.f32x2 %0, %1, %2, %0;" : "+l"(acc1[7]) : "l"(fb1), "l"((ull)q3.y));
        }
        __syncwarp();
    }
#pragma unroll
    for (int nn = 0; nn < 2; nn++) {
        int myNode = warpBase + lane + nn * 32;
        ull* acc = nn ? acc1 : acc0;
        if (myNode < N) {
            float v[16];
#pragma unroll
            for (int j = 0; j < 8; j++)
                asm("mov.b64 {%0, %1}, %2;" : "=f"(v[2 * j]), "=f"(v[2 * j + 1]) : "l"(acc[j]));
            __half2 l01 = __floats2half2_rn(v[0], v[1]);
            __half2 l23 = __floats2half2_rn(v[2], v[3]);
            __half2 l45 = __floats2half2_rn(v[4], v[5]);
            __half2 l67 = __floats2half2_rn(v[6], v[7]);
            uint4 u;
            u.x = *(unsigned*)&l01; u.y = *(unsigned*)&l23;
            u.z = *(unsigned*)&l45; u.w = *(unsigned*)&l67;
            g_elh[myNode] = u;
            __half2 r01 = __floats2half2_rn(v[8], v[9]);
            __half2 r23 = __floats2half2_rn(v[10], v[11]);
            __half2 r45 = __floats2half2_rn(v[12], v[13]);
            __half2 r67 = __floats2half2_rn(v[14], v[15]);
            uint4 q;
            q.x = *(unsigned*)&r01; q.y = *(unsigned*)&r23;
            q.z = *(unsigned*)&r45; q.w = *(unsigned*)&r67;
            g_erh[myNode] = q;
            float4 z = make_float4(0.f, 0.f, 0.f, 0.f);
            g_s4[(size_t)myNode * 2]     = z;
            g_s4[(size_t)myNode * 2 + 1] = z;
        }
    }
}

// ---------------------------------------------------------------------------
// K3: 1 thread per edge, all 8 heads. Logit combine fully in packed fp16:
// 8x HADD2 + 4x HMAX2 + one LDS.128 for the fp16 ee record, then 8x bare
// ex2.approx (tables prescaled by log2e). Per edge: 2 gather LDG.128,
// 2x red.global.add.v4 (fp32 accum), 1 coalesced STG.128 fp16 ex.
// Max-shift dropped (softmax shift-invariant; scaled logits in [0,~1.2]).
// ---------------------------------------------------------------------------
__global__ void __launch_bounds__(256) edge_expsum(const int* __restrict__ et,
                                                   const int* __restrict__ src,
                                                   const int* __restrict__ dst,
                                                   int E) {
    __shared__ __align__(16) __half2 seeh[TMAX * 4];   // 8 types x 4 half2 (16B/type)
    if (threadIdx.x < TMAX * 4) {
        float lo = g_ee[threadIdx.x * 2];
        float hi = g_ee[threadIdx.x * 2 + 1];
        seeh[threadIdx.x] = __floats2half2_rn(lo, hi);
    }
    __syncthreads();
    int e = blockIdx.x * 256 + threadIdx.x;
    if (e >= E) return;
    int s = __ldcs(&src[e]);
    int d = dst[e];
    int t = __ldcs(&et[e]);
    uint4 lu = __ldg(&g_elh[s]);
    uint4 ru = __ldg(&g_erh[d]);
    uint4 bu = *(const uint4*)(seeh + t * 4);          // one LDS.128
    __half2 z2 = __floats2half2_rn(0.f, 0.f);
    __half2 a01 = __hmax2(__hadd2(__hadd2(*(__half2*)&lu.x, *(__half2*)&ru.x), *(__half2*)&bu.x), z2);
    __half2 a23 = __hmax2(__hadd2(__hadd2(*(__half2*)&lu.y, *(__half2*)&ru.y), *(__half2*)&bu.y), z2);
    __half2 a45 = __hmax2(__hadd2(__hadd2(*(__half2*)&lu.z, *(__half2*)&ru.z), *(__half2*)&bu.z), z2);
    __half2 a67 = __hmax2(__hadd2(__hadd2(*(__half2*)&lu.w, *(__half2*)&ru.w), *(__half2*)&bu.w), z2);
    float2 f01 = __half22float2(a01);
    float2 f23 = __half22float2(a23);
    float2 f45 = __half22float2(a45);
    float2 f67 = __half22float2(a67);
    float x0, x1, x2, x3, x4, x5, x6, x7;
    asm("ex2.approx.ftz.f32 %0, %1;" : "=f"(x0) : "f"(f01.x));
    asm("ex2.approx.ftz.f32 %0, %1;" : "=f"(x1) : "f"(f01.y));
    asm("ex2.approx.ftz.f32 %0, %1;" : "=f"(x2) : "f"(f23.x));
    asm("ex2.approx.ftz.f32 %0, %1;" : "=f"(x3) : "f"(f23.y));
    asm("ex2.approx.ftz.f32 %0, %1;" : "=f"(x4) : "f"(f45.x));
    asm("ex2.approx.ftz.f32 %0, %1;" : "=f"(x5) : "f"(f45.y));
    asm("ex2.approx.ftz.f32 %0, %1;" : "=f"(x6) : "f"(f67.x));
    asm("ex2.approx.ftz.f32 %0, %1;" : "=f"(x7) : "f"(f67.y));
    float* sp = (float*)&g_s4[(size_t)d * 2];
    asm volatile("red.global.add.v4.f32 [%0], {%1,%2,%3,%4};"
                 :: "l"(sp), "f"(x0), "f"(x1), "f"(x2), "f"(x3) : "memory");
    asm volatile("red.global.add.v4.f32 [%0], {%1,%2,%3,%4};"
                 :: "l"(sp + 4), "f"(x4), "f"(x5), "f"(x6), "f"(x7) : "memory");
    __half2 h01 = __floats2half2_rn(x0, x1);
    __half2 h23 = __floats2half2_rn(x2, x3);
    __half2 h45 = __floats2half2_rn(x4, x5);
    __half2 h67 = __floats2half2_rn(x6, x7);
    ulonglong2 packed;
    asm("mov.b64 %0, {%1, %2};" : "=l"(packed.x)
        : "r"(*(unsigned*)&h01), "r"(*(unsigned*)&h23));
    asm("mov.b64 %0, {%1, %2};" : "=l"(packed.y)
        : "r"(*(unsigned*)&h45), "r"(*(unsigned*)&h67));
    g_ex[e] = packed;                    // default write-back: L2-resident
}

// ---------------------------------------------------------------------------
// K4: pack 1/s into fp16x8 (16B/node) so finalize gathers ONE line per edge.
// ---------------------------------------------------------------------------
__global__ void recip_pack(int N) {
    int i = blockIdx.x * 512 + threadIdx.x;
    if (i >= N) return;
    float4 s0 = g_s4[(size_t)i * 2];
    float4 s1 = g_s4[(size_t)i * 2 + 1];
    __half2 a = __floats2half2_rn(__fdividef(1.f, s0.x), __fdividef(1.f, s0.y));
    __half2 b = __floats2half2_rn(__fdividef(1.f, s0.z), __fdividef(1.f, s0.w));
    __half2 c = __floats2half2_rn(__fdividef(1.f, s1.x), __fdividef(1.f, s1.y));
    __half2 d = __floats2half2_rn(__fdividef(1.f, s1.z), __fdividef(1.f, s1.w));
    uint4 u;
    u.x = *(unsigned*)&a; u.y = *(unsigned*)&b;
    u.z = *(unsigned*)&c; u.w = *(unsigned*)&d;
    g_sinv[i] = u;
}

// ---------------------------------------------------------------------------
// K5 (finalize): out = ex * sinv[dst]. 1 thread/edge: dst 4B (L2 hit) + ex
// LDG.128 (L2 hit) + ONE scattered LDG.128 (sinv) + 2 streaming STG.128.
// ---------------------------------------------------------------------------
__global__ void __launch_bounds__(256) finalize(const int* __restrict__ dst,
                                                float* __restrict__ out,
                                                int E) {
    int e = blockIdx.x * 256 + threadIdx.x;
    if (e >= E) return;
    int d = dst[e];
    ulonglong2 p = g_ex[e];
    uint4 si = __ldg(&g_sinv[d]);
    unsigned a0, a1, a2, a3;
    asm("mov.b64 {%0, %1}, %2;" : "=r"(a0), "=r"(a1) : "l"(p.x));
    asm("mov.b64 {%0, %1}, %2;" : "=r"(a2), "=r"(a3) : "l"(p.y));
    float2 x01 = __half22float2(*(__half2*)&a0);
    float2 x23 = __half22float2(*(__half2*)&a1);
    float2 x45 = __half22float2(*(__half2*)&a2);
    float2 x67 = __half22float2(*(__half2*)&a3);
    float2 i01 = __half22float2(*(__half2*)&si.x);
    float2 i23 = __half22float2(*(__half2*)&si.y);
    float2 i45 = __half22float2(*(__half2*)&si.z);
    float2 i67 = __half22float2(*(__half2*)&si.w);
    float4 o0, o1;
    o0.x = x01.x * i01.x;
    o0.y = x01.y * i01.y;
    o0.z = x23.x * i23.x;
    o0.w = x23.y * i23.y;
    o1.x = x45.x * i45.x;
    o1.y = x45.y * i45.y;
    o1.z = x67.x * i67.x;
    o1.w = x67.y * i67.y;
    __stcs((float4*)(out + (size_t)e * 8), o0);
    __stcs((float4*)(out + (size_t)e * 8) + 1, o1);
}

// ---------------------------------------------------------------------------
extern "C" void kernel_launch(void* const* d_in, const int* in_sizes, int n_in,
                              void* d_out, int out_size) {
    const float* feat     = (const float*)d_in[0];
    const int*   etype    = (const int*)  d_in[1];
    const int*   src      = (const int*)  d_in[2];
    const int*   dst      = (const int*)  d_in[3];
    const float* W_fc     = (const float*)d_in[4];
    const float* edge_emb = (const float*)d_in[5];
    const float* W_e      = (const float*)d_in[6];
    const float* attn_l   = (const float*)d_in[7];
    const float* attn_r   = (const float*)d_in[8];
    const float* attn_e   = (const float*)d_in[9];
    float* out = (float*)d_out;

    int N = in_sizes[0] / IN_F;
    int E = in_sizes[1];

    setup<<<IN_F + TMAX, 256>>>(W_fc, attn_l, attn_r, edge_emb, W_e, attn_e);
    node_proj<<<(N + 255) / 256, 128>>>(feat, N);
    edge_expsum<<<(E + 255) / 256, 256>>>(etype, src, dst, E);
    recip_pack<<<(N + 511) / 512, 512>>>(N);
    finalize<<<(E + 255) / 256, 256>>>(dst, out, E);
}